// round 11
// baseline (speedup 1.0000x reference)
#include <cuda_runtime.h>
#include <cuda_bf16.h>
#include <cstdint>

// Problem constants
#define NBLK   4
#define DIM    256
#define DSTATE 16
#define DCONV  4
#define DIN    512      // EXPAND * DIM
#define DTRANK 16
#define BB     16
#define LL     512
#define TOK    (BB * LL)              // 8192 tokens
#define DBC_N  (DTRANK + 2 * DSTATE)  // 48

// ---------------------------------------------------------------------------
// Scratch (static device globals; no runtime allocation allowed)
// ---------------------------------------------------------------------------
__device__ __align__(16) __nv_bfloat16 g_h_hi [TOK * DIM];
__device__ __align__(16) __nv_bfloat16 g_h_lo [TOK * DIM];
__device__ __align__(16) float         g_xin  [TOK * DIN];
__device__ __align__(16) float         g_silz [TOK * DIN];
__device__ __align__(16) float         g_xc   [TOK * DIN];
__device__ __align__(16) __nv_bfloat16 g_xc_hi[TOK * DIN];
__device__ __align__(16) __nv_bfloat16 g_xc_lo[TOK * DIN];
__device__ __align__(16) float         g_dbc  [TOK * DBC_N];
__device__ __align__(16) float         g_dt   [TOK * DIN];
__device__ __align__(16) __nv_bfloat16 g_g_hi [TOK * DIN];
__device__ __align__(16) __nv_bfloat16 g_g_lo [TOK * DIN];
// per-block weight splits (converted once per block)
__device__ __align__(16) __nv_bfloat16 g_win_hi[2 * DIN * DIM];
__device__ __align__(16) __nv_bfloat16 g_win_lo[2 * DIN * DIM];
__device__ __align__(16) __nv_bfloat16 g_wxp_hi[DBC_N * DIN];
__device__ __align__(16) __nv_bfloat16 g_wxp_lo[DBC_N * DIN];
__device__ __align__(16) __nv_bfloat16 g_wow_hi[DIM * DIN];
__device__ __align__(16) __nv_bfloat16 g_wow_lo[DIM * DIN];

// ---------------------------------------------------------------------------
// Helpers
// ---------------------------------------------------------------------------
__device__ __forceinline__ float siluf(float v) {
    return v / (1.0f + __expf(-v));
}
__device__ __forceinline__ float softplusf(float v) {
    return (v > 20.0f) ? v : log1pf(__expf(v));
}
__device__ __forceinline__ uint32_t smem_u32(const void* p) {
    uint32_t a;
    asm("{ .reg .u64 t; cvta.to.shared.u64 t, %1; cvt.u32.u64 %0, t; }"
        : "=r"(a) : "l"(p));
    return a;
}
__device__ __forceinline__ uint32_t pack_bf16(__nv_bfloat16 a, __nv_bfloat16 b) {
    return (uint32_t)__bfloat16_as_ushort(a) |
           ((uint32_t)__bfloat16_as_ushort(b) << 16);
}
__device__ __forceinline__ void split4(float4 v, uint2& hi, uint2& lo) {
    __nv_bfloat16 h0 = __float2bfloat16(v.x);
    __nv_bfloat16 h1 = __float2bfloat16(v.y);
    __nv_bfloat16 h2 = __float2bfloat16(v.z);
    __nv_bfloat16 h3 = __float2bfloat16(v.w);
    __nv_bfloat16 l0 = __float2bfloat16(v.x - __bfloat162float(h0));
    __nv_bfloat16 l1 = __float2bfloat16(v.y - __bfloat162float(h1));
    __nv_bfloat16 l2 = __float2bfloat16(v.z - __bfloat162float(h2));
    __nv_bfloat16 l3 = __float2bfloat16(v.w - __bfloat162float(h3));
    hi = make_uint2(pack_bf16(h0, h1), pack_bf16(h2, h3));
    lo = make_uint2(pack_bf16(l0, l1), pack_bf16(l2, l3));
}

// mma.sync m16n8k16 bf16 (baseline PTX, sm_80+; legal on compute_103)
__device__ __forceinline__ void mma16816(float* c, const uint32_t* a,
                                         const uint32_t* b) {
    asm volatile(
        "mma.sync.aligned.m16n8k16.row.col.f32.bf16.bf16.f32 "
        "{%0,%1,%2,%3}, {%4,%5,%6,%7}, {%8,%9}, {%0,%1,%2,%3};"
        : "+f"(c[0]), "+f"(c[1]), "+f"(c[2]), "+f"(c[3])
        : "r"(a[0]), "r"(a[1]), "r"(a[2]), "r"(a[3]), "r"(b[0]), "r"(b[1]));
}
__device__ __forceinline__ void ldm_x4(uint32_t* r, uint32_t addr) {
    asm volatile("ldmatrix.sync.aligned.m8n8.x4.shared.b16 {%0,%1,%2,%3}, [%4];"
                 : "=r"(r[0]), "=r"(r[1]), "=r"(r[2]), "=r"(r[3]) : "r"(addr));
}
__device__ __forceinline__ void cp16(uint32_t dst, const void* src) {
    asm volatile("{ .reg .u64 g; cvta.to.global.u64 g, %1; "
                 "cp.async.ca.shared.global [%0], [g], 16; }"
                 :: "r"(dst), "l"(src));
}
#define CP_COMMIT() asm volatile("cp.async.commit_group;" ::: "memory")
#define CP_WAIT(n)  asm volatile("cp.async.wait_group %0;" :: "n"(n) : "memory")

// ===========================================================================
// Weight split kernel: fp32 -> bf16 hi/lo (once per block per weight)
// ===========================================================================
__global__ void wsplit_kernel(const float* __restrict__ w,
                              __nv_bfloat16* __restrict__ hi,
                              __nv_bfloat16* __restrict__ lo, int n4)
{
    int i = blockIdx.x * blockDim.x + threadIdx.x;
    if (i >= n4) return;
    float4 v = reinterpret_cast<const float4*>(w)[i];
    uint2 h, l;
    split4(v, h, l);
    reinterpret_cast<uint2*>(hi)[i] = h;
    reinterpret_cast<uint2*>(lo)[i] = l;
}

// ===========================================================================
// Main bf16 HMMA GEMM (in_proj / out_proj): C[M,N] = A[M,K] @ W[N,K]^T
// 3-term hi/lo split for fp32-class accuracy. CTA 128x128, 8 warps (2m x 4n,
// warp tile 64x32). K-chunk 64, double-buffered cp.async.
// MODE 0: +bias, col<DIN -> C0 (xin), col>=DIN -> silu -> C1 (silz)
// MODE 2: C0 = C1 + v (residual)
// ===========================================================================
#define LDT 72                       // bf16 elems per smem row (64 + 8 pad)
#define KC  64
#define STG_BIG (4 * 128 * LDT)      // elems per stage (Ahi,Alo,Whi,Wlo)
#define SMEM_BIG (2 * STG_BIG * 2)   // bytes (double buffered)

template<int MODE, int KTOT>
__global__ void __launch_bounds__(256)
gemm_bf16(const __nv_bfloat16* __restrict__ Ahi,
          const __nv_bfloat16* __restrict__ Alo,
          const __nv_bfloat16* __restrict__ Whi,
          const __nv_bfloat16* __restrict__ Wlo,
          const float* __restrict__ bias,
          float* __restrict__ C0, float* __restrict__ C1, int N)
{
    extern __shared__ __nv_bfloat16 sm[];
    const uint32_t sb = smem_u32(sm);
    const int tid  = threadIdx.x;
    const int lane = tid & 31;
    const int wid  = tid >> 5;
    const int wm   = wid & 1;
    const int wn   = wid >> 1;
    const int m0   = blockIdx.y * 128;
    const int n0   = blockIdx.x * 128;

    float acc[4][4][4];
    #pragma unroll
    for (int i = 0; i < 4; i++)
        #pragma unroll
        for (int j = 0; j < 4; j++)
            #pragma unroll
            for (int k = 0; k < 4; k++) acc[i][j][k] = 0.0f;

    const int arow = wm * 64 + (lane & 15);
    const int acol = (lane >> 4) * 8;
    const int bgrp = lane >> 3;
    const int brow = wn * 32 + (lane & 7) + ((bgrp >> 1) << 3);
    const int bcol = (bgrp & 1) * 8;

    constexpr int NCH = KTOT / KC;

    auto copy_chunk = [&](int stg, int k0) {
        uint32_t base = sb + (uint32_t)stg * STG_BIG * 2;
        #pragma unroll
        for (int j = 0; j < 4; j++) {       // Ahi: 1024 vec16 / 256 thr
            int i = tid + j * 256, r = i >> 3, c8 = i & 7;
            cp16(base + (uint32_t)(r * LDT + c8 * 8) * 2,
                 Ahi + (size_t)(m0 + r) * KTOT + k0 + c8 * 8);
        }
        #pragma unroll
        for (int j = 0; j < 4; j++) {       // Alo
            int i = tid + j * 256, r = i >> 3, c8 = i & 7;
            cp16(base + (uint32_t)(128 * LDT + r * LDT + c8 * 8) * 2,
                 Alo + (size_t)(m0 + r) * KTOT + k0 + c8 * 8);
        }
        #pragma unroll
        for (int j = 0; j < 4; j++) {       // Whi
            int i = tid + j * 256, r = i >> 3, c8 = i & 7;
            cp16(base + (uint32_t)(2 * 128 * LDT + r * LDT + c8 * 8) * 2,
                 Whi + (size_t)(n0 + r) * KTOT + k0 + c8 * 8);
        }
        #pragma unroll
        for (int j = 0; j < 4; j++) {       // Wlo
            int i = tid + j * 256, r = i >> 3, c8 = i & 7;
            cp16(base + (uint32_t)(3 * 128 * LDT + r * LDT + c8 * 8) * 2,
                 Wlo + (size_t)(n0 + r) * KTOT + k0 + c8 * 8);
        }
    };

    copy_chunk(0, 0);
    CP_COMMIT();

    for (int ch = 0; ch < NCH; ch++) {
        if (ch + 1 < NCH) {
            copy_chunk((ch + 1) & 1, (ch + 1) * KC);
            CP_COMMIT();
            CP_WAIT(1);
        } else {
            CP_WAIT(0);
        }
        __syncthreads();

        const uint32_t stb  = sb + (uint32_t)(ch & 1) * STG_BIG * 2;
        const uint32_t pAhi = stb;
        const uint32_t pAlo = stb + 128 * LDT * 2;
        const uint32_t pWhi = stb + 2 * 128 * LDT * 2;
        const uint32_t pWlo = stb + 3 * 128 * LDT * 2;

        #pragma unroll
        for (int kk = 0; kk < 4; kk++) {
            uint32_t ahi[4][4], alo[4][4];
            #pragma unroll
            for (int mi = 0; mi < 4; mi++) {
                uint32_t off = (uint32_t)(((arow + mi * 16) * LDT) + kk * 16 + acol) * 2;
                ldm_x4(ahi[mi], pAhi + off);
                ldm_x4(alo[mi], pAlo + off);
            }
            uint32_t bhi[8], blo[8];
            #pragma unroll
            for (int ni = 0; ni < 2; ni++) {
                uint32_t off = (uint32_t)(((brow + ni * 16) * LDT) + kk * 16 + bcol) * 2;
                ldm_x4(bhi + ni * 4, pWhi + off);
                ldm_x4(blo + ni * 4, pWlo + off);
            }
            #pragma unroll
            for (int mi = 0; mi < 4; mi++)
                #pragma unroll
                for (int nj = 0; nj < 4; nj++) {
                    mma16816(acc[mi][nj], ahi[mi], bhi + nj * 2);
                    mma16816(acc[mi][nj], ahi[mi], blo + nj * 2);
                    mma16816(acc[mi][nj], alo[mi], bhi + nj * 2);
                }
        }
        __syncthreads();
    }

    // -------- epilogue --------
    const int r0 = lane >> 2;
    const int c0 = (lane & 3) * 2;
    #pragma unroll
    for (int mi = 0; mi < 4; mi++) {
        #pragma unroll
        for (int nj = 0; nj < 4; nj++) {
            int row = m0 + wm * 64 + mi * 16 + r0;
            int col = n0 + wn * 32 + nj * 8 + c0;
            #pragma unroll
            for (int half = 0; half < 2; half++) {
                int rr = row + half * 8;
                float v0 = acc[mi][nj][half * 2 + 0];
                float v1 = acc[mi][nj][half * 2 + 1];
                if (MODE == 0) {
                    v0 += bias[col];
                    v1 += bias[col + 1];
                    if (n0 < DIN) {
                        *reinterpret_cast<float2*>(C0 + (size_t)rr * DIN + col)
                            = make_float2(v0, v1);
                    } else {
                        *reinterpret_cast<float2*>(C1 + (size_t)rr * DIN + (col - DIN))
                            = make_float2(siluf(v0), siluf(v1));
                    }
                } else {
                    float2 rv = *reinterpret_cast<const float2*>(
                        C1 + (size_t)rr * N + col);
                    *reinterpret_cast<float2*>(C0 + (size_t)rr * N + col)
                        = make_float2(rv.x + v0, rv.y + v1);
                }
            }
        }
    }
}

// ===========================================================================
// x_proj HMMA GEMM: dbc[8192,48] = xc[8192,512] @ xpw[48,512]^T
// CTA 64(M) x 48(N), 4 warps (each 16x48). K-chunk 64, double-buffered.
// ===========================================================================
#define XA_LO (64 * LDT)
#define XW_HI (128 * LDT)
#define XW_LO (176 * LDT)
#define STG_XP (224 * LDT)
#define SMEM_XP (2 * STG_XP * 2)

__global__ void __launch_bounds__(128)
xproj_mma(const __nv_bfloat16* __restrict__ Ahi,
          const __nv_bfloat16* __restrict__ Alo,
          const __nv_bfloat16* __restrict__ Whi,
          const __nv_bfloat16* __restrict__ Wlo,
          float* __restrict__ C0)
{
    constexpr int KTOT = DIN;   // 512
    extern __shared__ __nv_bfloat16 sm[];
    const uint32_t sb = smem_u32(sm);
    const int tid  = threadIdx.x;
    const int lane = tid & 31;
    const int wid  = tid >> 5;          // 0..3
    const int m0   = blockIdx.y * 64;

    float acc[6][4];
    #pragma unroll
    for (int i = 0; i < 6; i++)
        #pragma unroll
        for (int k = 0; k < 4; k++) acc[i][k] = 0.0f;

    const int arow = wid * 16 + (lane & 15);
    const int acol = (lane >> 4) * 8;
    const int bgrp = lane >> 3;
    const int brow = (lane & 7) + ((bgrp >> 1) << 3);
    const int bcol = (bgrp & 1) * 8;

    constexpr int NCH = KTOT / KC;      // 8

    auto copy_chunk = [&](int stg, int k0) {
        uint32_t base = sb + (uint32_t)stg * STG_XP * 2;
        #pragma unroll
        for (int j = 0; j < 4; j++) {   // Ahi: 512 vec / 128 thr
            int i = tid + j * 128, r = i >> 3, c8 = i & 7;
            cp16(base + (uint32_t)(r * LDT + c8 * 8) * 2,
                 Ahi + (size_t)(m0 + r) * KTOT + k0 + c8 * 8);
        }
        #pragma unroll
        for (int j = 0; j < 4; j++) {   // Alo
            int i = tid + j * 128, r = i >> 3, c8 = i & 7;
            cp16(base + (uint32_t)(XA_LO + r * LDT + c8 * 8) * 2,
                 Alo + (size_t)(m0 + r) * KTOT + k0 + c8 * 8);
        }
        #pragma unroll
        for (int j = 0; j < 3; j++) {   // Whi: 384 vec
            int i = tid + j * 128, r = i >> 3, c8 = i & 7;
            cp16(base + (uint32_t)(XW_HI + r * LDT + c8 * 8) * 2,
                 Whi + (size_t)r * KTOT + k0 + c8 * 8);
        }
        #pragma unroll
        for (int j = 0; j < 3; j++) {   // Wlo
            int i = tid + j * 128, r = i >> 3, c8 = i & 7;
            cp16(base + (uint32_t)(XW_LO + r * LDT + c8 * 8) * 2,
                 Wlo + (size_t)r * KTOT + k0 + c8 * 8);
        }
    };

    copy_chunk(0, 0);
    CP_COMMIT();

    for (int ch = 0; ch < NCH; ch++) {
        if (ch + 1 < NCH) {
            copy_chunk((ch + 1) & 1, (ch + 1) * KC);
            CP_COMMIT();
            CP_WAIT(1);
        } else {
            CP_WAIT(0);
        }
        __syncthreads();

        const uint32_t stb  = sb + (uint32_t)(ch & 1) * STG_XP * 2;
        const uint32_t pAhi = stb;
        const uint32_t pAlo = stb + XA_LO * 2;
        const uint32_t pWhi = stb + XW_HI * 2;
        const uint32_t pWlo = stb + XW_LO * 2;

        #pragma unroll
        for (int kk = 0; kk < 4; kk++) {
            uint32_t ahi[4], alo[4];
            uint32_t aoff = (uint32_t)((arow * LDT) + kk * 16 + acol) * 2;
            ldm_x4(ahi, pAhi + aoff);
            ldm_x4(alo, pAlo + aoff);
            uint32_t bhi[12], blo[12];
            #pragma unroll
            for (int ni = 0; ni < 3; ni++) {
                uint32_t off = (uint32_t)(((brow + ni * 16) * LDT) + kk * 16 + bcol) * 2;
                ldm_x4(bhi + ni * 4, pWhi + off);
                ldm_x4(blo + ni * 4, pWlo + off);
            }
            #pragma unroll
            for (int nj = 0; nj < 6; nj++) {
                mma16816(acc[nj], ahi, bhi + nj * 2);
                mma16816(acc[nj], ahi, blo + nj * 2);
                mma16816(acc[nj], alo, bhi + nj * 2);
            }
        }
        __syncthreads();
    }

    const int r0 = lane >> 2;
    const int c0 = (lane & 3) * 2;
    #pragma unroll
    for (int nj = 0; nj < 6; nj++) {
        #pragma unroll
        for (int half = 0; half < 2; half++) {
            int row = m0 + wid * 16 + r0 + half * 8;
            int col = nj * 8 + c0;
            *reinterpret_cast<float2*>(C0 + (size_t)row * DBC_N + col)
                = make_float2(acc[nj][half * 2], acc[nj][half * 2 + 1]);
        }
    }
}

// ---------------------------------------------------------------------------
// LayerNorm: one warp per token; writes bf16 hi/lo directly.
// ---------------------------------------------------------------------------
__global__ void ln_kernel(const float* __restrict__ x,
                          const float* __restrict__ w,
                          const float* __restrict__ b,
                          __nv_bfloat16* __restrict__ out_hi,
                          __nv_bfloat16* __restrict__ out_lo)
{
    int warpsPerBlock = blockDim.x >> 5;
    int t    = blockIdx.x * warpsPerBlock + (threadIdx.x >> 5);
    int lane = threadIdx.x & 31;
    if (t >= TOK) return;

    const float4* xr = reinterpret_cast<const float4*>(x + (size_t)t * DIM);
    float4 v0 = xr[lane];
    float4 v1 = xr[lane + 32];

    float s  = v0.x + v0.y + v0.z + v0.w + v1.x + v1.y + v1.z + v1.w;
    float ss = v0.x*v0.x + v0.y*v0.y + v0.z*v0.z + v0.w*v0.w
             + v1.x*v1.x + v1.y*v1.y + v1.z*v1.z + v1.w*v1.w;
    #pragma unroll
    for (int o = 16; o > 0; o >>= 1) {
        s  += __shfl_xor_sync(0xffffffffu, s,  o);
        ss += __shfl_xor_sync(0xffffffffu, ss, o);
    }
    float mu  = s * (1.0f / DIM);
    float var = ss * (1.0f / DIM) - mu * mu;
    float inv = rsqrtf(var + 1e-5f);

    const float4* wr = reinterpret_cast<const float4*>(w);
    const float4* br = reinterpret_cast<const float4*>(b);
    float4 w0 = wr[lane], w1 = wr[lane + 32];
    float4 b0 = br[lane], b1 = br[lane + 32];

    float4 o0, o1;
    o0.x = (v0.x - mu) * inv * w0.x + b0.x;
    o0.y = (v0.y - mu) * inv * w0.y + b0.y;
    o0.z = (v0.z - mu) * inv * w0.z + b0.z;
    o0.w = (v0.w - mu) * inv * w0.w + b0.w;
    o1.x = (v1.x - mu) * inv * w1.x + b1.x;
    o1.y = (v1.y - mu) * inv * w1.y + b1.y;
    o1.z = (v1.z - mu) * inv * w1.z + b1.z;
    o1.w = (v1.w - mu) * inv * w1.w + b1.w;

    uint2 hi, lo;
    uint2* ph = reinterpret_cast<uint2*>(out_hi + (size_t)t * DIM);
    uint2* pl = reinterpret_cast<uint2*>(out_lo + (size_t)t * DIM);
    split4(o0, hi, lo);
    ph[lane] = hi;  pl[lane] = lo;
    split4(o1, hi, lo);
    ph[lane + 32] = hi;  pl[lane + 32] = lo;
}

// ---------------------------------------------------------------------------
// Causal depthwise conv (DCONV=4) + bias + SiLU; writes fp32 + bf16 hi/lo.
// ---------------------------------------------------------------------------
__global__ void conv_kernel(const float* __restrict__ xin,
                            const float* __restrict__ cw,
                            const float* __restrict__ cb,
                            float* __restrict__ xc,
                            __nv_bfloat16* __restrict__ xc_hi,
                            __nv_bfloat16* __restrict__ xc_lo)
{
    int idx = blockIdx.x * blockDim.x + threadIdx.x;
    if (idx >= TOK * DIN) return;
    int c = idx % DIN;
    int t = idx / DIN;
    int l = t % LL;

    float w0 = cw[c * DCONV + 0];
    float w1 = cw[c * DCONV + 1];
    float w2 = cw[c * DCONV + 2];
    float w3 = cw[c * DCONV + 3];

    float acc = cb[c];
    if (l >= 3) acc = fmaf(xin[idx - 3 * DIN], w0, acc);
    if (l >= 2) acc = fmaf(xin[idx - 2 * DIN], w1, acc);
    if (l >= 1) acc = fmaf(xin[idx - 1 * DIN], w2, acc);
    acc = fmaf(xin[idx], w3, acc);
    float r = siluf(acc);
    xc[idx] = r;
    __nv_bfloat16 h = __float2bfloat16(r);
    xc_hi[idx] = h;
    xc_lo[idx] = __float2bfloat16(r - __bfloat162float(h));
}

// ---------------------------------------------------------------------------
// dt = softplus( dbc[:, :DTRANK] @ dtw^T + dtb ).
// ---------------------------------------------------------------------------
__global__ void dt_kernel(const float* __restrict__ dbc,
                          const float* __restrict__ dtw,
                          const float* __restrict__ dtb,
                          float* __restrict__ dt)
{
    int idx = blockIdx.x * blockDim.x + threadIdx.x;
    if (idx >= TOK * DIN) return;
    int d = idx % DIN;
    int t = idx / DIN;

    const float* r  = dbc + (size_t)t * DBC_N;
    const float* wv = dtw + (size_t)d * DTRANK;
    float acc = dtb[d];
    #pragma unroll
    for (int i = 0; i < DTRANK; i++) acc = fmaf(r[i], wv[i], acc);
    dt[idx] = softplusf(acc);
}

// ---------------------------------------------------------------------------
// Selective scan + gating; writes g as bf16 hi/lo (for out_proj HMMA).
// ---------------------------------------------------------------------------
__global__ void __launch_bounds__(256)
scan_kernel(const float* __restrict__ dt,
            const float* __restrict__ dbc,
            const float* __restrict__ u,      // xc
            const float* __restrict__ A_log,
            const float* __restrict__ Dv,
            const float* __restrict__ silz,
            __nv_bfloat16* __restrict__ g_hi,
            __nv_bfloat16* __restrict__ g_lo)
{
    int tid = threadIdx.x;
    int n   = tid & 15;
    int ch  = blockIdx.x * 16 + (tid >> 4);
    int b   = ch >> 9;
    int d   = ch & (DIN - 1);

    float An = -__expf(A_log[d * DSTATE + n]);
    float Dd = Dv[d];
    float h  = 0.0f;
    int tbase = b * LL;

    #pragma unroll 4
    for (int l = 0; l < LL; l++) {
        int t = tbase + l;
        float dtv = dt[(size_t)t * DIN + d];
        float uv  = u [(size_t)t * DIN + d];
        float Bn  = dbc[(size_t)t * DBC_N + DTRANK + n];
        float Cn  = dbc[(size_t)t * DBC_N + DTRANK + DSTATE + n];

        float dA = __expf(dtv * An);
        h = fmaf(dA, h, dtv * Bn * uv);

        float p = h * Cn;
        p += __shfl_xor_sync(0xffffffffu, p, 8);
        p += __shfl_xor_sync(0xffffffffu, p, 4);
        p += __shfl_xor_sync(0xffffffffu, p, 2);
        p += __shfl_xor_sync(0xffffffffu, p, 1);

        if (n == 0) {
            float y  = p + uv * Dd;
            float gg = y * silz[(size_t)t * DIN + d];
            __nv_bfloat16 hh = __float2bfloat16(gg);
            g_hi[(size_t)t * DIN + d] = hh;
            g_lo[(size_t)t * DIN + d] =
                __float2bfloat16(gg - __bfloat162float(hh));
        }
    }
}

// ---------------------------------------------------------------------------
// Launcher
// ---------------------------------------------------------------------------
extern "C" void kernel_launch(void* const* d_in, const int* in_sizes, int n_in,
                              void* d_out, int out_size)
{
    const float* x    = (const float*)d_in[0];
    const float* ln_w = (const float*)d_in[1];
    const float* ln_b = (const float*)d_in[2];
    const float* in_w = (const float*)d_in[3];
    const float* in_b = (const float*)d_in[4];
    const float* cw   = (const float*)d_in[5];
    const float* cb   = (const float*)d_in[6];
    const float* xp_w = (const float*)d_in[7];
    const float* dt_w = (const float*)d_in[8];
    const float* dt_b = (const float*)d_in[9];
    const float* A_lg = (const float*)d_in[10];
    const float* Dv   = (const float*)d_in[11];
    const float* ow   = (const float*)d_in[12];

    __nv_bfloat16 *p_hhi, *p_hlo, *p_xchi, *p_xclo, *p_ghi, *p_glo;
    __nv_bfloat16 *p_winh, *p_winl, *p_wxph, *p_wxpl, *p_wowh, *p_wowl;
    float *p_xin, *p_silz, *p_xc, *p_dbc, *p_dt;
    cudaGetSymbolAddress((void**)&p_hhi,  g_h_hi);
    cudaGetSymbolAddress((void**)&p_hlo,  g_h_lo);
    cudaGetSymbolAddress((void**)&p_xin,  g_xin);
    cudaGetSymbolAddress((void**)&p_silz, g_silz);
    cudaGetSymbolAddress((void**)&p_xc,   g_xc);
    cudaGetSymbolAddress((void**)&p_xchi, g_xc_hi);
    cudaGetSymbolAddress((void**)&p_xclo, g_xc_lo);
    cudaGetSymbolAddress((void**)&p_dbc,  g_dbc);
    cudaGetSymbolAddress((void**)&p_dt,   g_dt);
    cudaGetSymbolAddress((void**)&p_ghi,  g_g_hi);
    cudaGetSymbolAddress((void**)&p_glo,  g_g_lo);
    cudaGetSymbolAddress((void**)&p_winh, g_win_hi);
    cudaGetSymbolAddress((void**)&p_winl, g_win_lo);
    cudaGetSymbolAddress((void**)&p_wxph, g_wxp_hi);
    cudaGetSymbolAddress((void**)&p_wxpl, g_wxp_lo);
    cudaGetSymbolAddress((void**)&p_wowh, g_wow_hi);
    cudaGetSymbolAddress((void**)&p_wowl, g_wow_lo);

    cudaFuncSetAttribute(gemm_bf16<0, DIM>,
                         cudaFuncAttributeMaxDynamicSharedMemorySize, SMEM_BIG);
    cudaFuncSetAttribute(gemm_bf16<2, DIN>,
                         cudaFuncAttributeMaxDynamicSharedMemorySize, SMEM_BIG);
    cudaFuncSetAttribute(xproj_mma,
                         cudaFuncAttributeMaxDynamicSharedMemorySize, SMEM_XP);

    float* xres = (float*)d_out;  // running residual buffer (= final output)
    cudaMemcpyAsync(xres, x, (size_t)TOK * DIM * sizeof(float),
                    cudaMemcpyDeviceToDevice, 0);

    for (int nb = 0; nb < NBLK; nb++) {
        const float* lnw = ln_w + nb * DIM;
        const float* lnb = ln_b + nb * DIM;
        const float* inw = in_w + (size_t)nb * 2 * DIN * DIM;
        const float* inb = in_b + nb * 2 * DIN;
        const float* cwn = cw   + (size_t)nb * DIN * DCONV;
        const float* cbn = cb   + nb * DIN;
        const float* xpw = xp_w + (size_t)nb * DBC_N * DIN;
        const float* dtw = dt_w + (size_t)nb * DIN * DTRANK;
        const float* dtb = dt_b + nb * DIN;
        const float* alg = A_lg + (size_t)nb * DIN * DSTATE;
        const float* dvn = Dv   + nb * DIN;
        const float* own = ow   + (size_t)nb * DIM * DIN;

        // 0. Split this block's weights into bf16 hi/lo (once per block)
        wsplit_kernel<<<(2 * DIN * DIM / 4 + 255) / 256, 256>>>(
            inw, p_winh, p_winl, 2 * DIN * DIM / 4);
        wsplit_kernel<<<(DBC_N * DIN / 4 + 255) / 256, 256>>>(
            xpw, p_wxph, p_wxpl, DBC_N * DIN / 4);
        wsplit_kernel<<<(DIM * DIN / 4 + 255) / 256, 256>>>(
            own, p_wowh, p_wowl, DIM * DIN / 4);

        // 1. LayerNorm -> h (bf16 hi/lo)
        ln_kernel<<<TOK / 8, 256>>>(xres, lnw, lnb, p_hhi, p_hlo);

        // 2. in_proj GEMM (HMMA, pipelined): (8192,256)@(256,1024)
        gemm_bf16<0, DIM><<<dim3(2 * DIN / 128, TOK / 128), 256, SMEM_BIG>>>(
            p_hhi, p_hlo, p_winh, p_winl, inb, p_xin, p_silz, 2 * DIN);

        // 3. Causal depthwise conv + SiLU -> xc (fp32 + bf16 hi/lo)
        conv_kernel<<<(TOK * DIN) / 256, 256>>>(
            p_xin, cwn, cbn, p_xc, p_xchi, p_xclo);

        // 4. x_proj GEMM (HMMA): (8192,512)@(512,48) -> dbc
        xproj_mma<<<dim3(1, TOK / 64), 128, SMEM_XP>>>(
            p_xchi, p_xclo, p_wxph, p_wxpl, p_dbc);

        // 5. dt projection + softplus
        dt_kernel<<<(TOK * DIN) / 256, 256>>>(p_dbc, dtw, dtb, p_dt);

        // 6. Selective scan + D skip + gating -> g (bf16 hi/lo)
        scan_kernel<<<(BB * DIN) / 16, 256>>>(
            p_dt, p_dbc, p_xc, alg, dvn, p_silz, p_ghi, p_glo);

        // 7. out_proj GEMM (HMMA) + residual: xres += g @ ow^T
        gemm_bf16<2, DIN><<<dim3(DIM / 128, TOK / 128), 256, SMEM_BIG>>>(
            p_ghi, p_glo, p_wowh, p_wowl, nullptr, xres, xres, DIM);
    }
}